// round 17
// baseline (speedup 1.0000x reference)
#include <cuda_runtime.h>
#include <cuda_bf16.h>
#include <cstdint>

#define TLEN   128
#define HID    768
#define LHU    256
#define G4     1024
#define S_TOT  256
#define BATCH  8
#define NSENT  32
#define NCTA   128

typedef unsigned long long u64;

// ---------------- device scratch ----------------
__device__ float g_G    [2][(size_t)S_TOT * TLEN * G4];  // word pre-gates, gate-interleaved cols (4u+g)
__device__ float g_emb  [S_TOT * 2 * LHU];
__device__ float g_WshhX[2][LHU * LHU * 4];
__device__ float g_Gs   [2][S_TOT * G4];
__device__ float g_final[BATCH * 2 * LHU];
__device__ float g_wihX [2][G4 * HID];                   // word Wih rows permuted to 4u+g
__device__ float g_biasX[2][G4];
__device__ float g_WhhHi[2][G4 * LHU];                   // word Whh rows 4u+g, tf32-rounded

// ---------------- helpers ----------------
__device__ __forceinline__ float sigf(float x) { return 1.f / (1.f + __expf(-x)); }
__device__ __forceinline__ float tanh_(float x) {
    float e = __expf(-2.f * fabsf(x));
    float r = (1.f - e) / (1.f + e);
    return copysignf(r, x);
}
__device__ __forceinline__ uint32_t tf32r(float f) {
    uint32_t o;
    asm("cvt.rna.tf32.f32 %0, %1;" : "=r"(o) : "f"(f));
    return o;
}
#define MMA_TF32(cc, a, b)                                              \
    asm volatile(                                                       \
        "mma.sync.aligned.m16n8k8.row.col.f32.tf32.tf32.f32 "           \
        "{%0,%1,%2,%3}, {%4,%5,%6,%7}, {%8,%9}, {%0,%1,%2,%3};"         \
        : "+f"((cc)[0]), "+f"((cc)[1]), "+f"((cc)[2]), "+f"((cc)[3])    \
        : "r"((a)[0]), "r"((a)[1]), "r"((a)[2]), "r"((a)[3]),           \
          "r"((b)[0]), "r"((b)[1]))
#define CLUSTER_SYNC() do {                                             \
    asm volatile("barrier.cluster.arrive.aligned;" ::: "memory");       \
    asm volatile("barrier.cluster.wait.aligned;" ::: "memory");         \
} while (0)

// ---------------- tf32 mma.sync GEMM, CTA 128x256, 8 warps (2M x 4N), warp 64x64 ----------------
#define GEMM_SMEM ((128 * 36 + 256 * 36) * 4)
__global__ void __launch_bounds__(256) mma_gemm(
    const float* __restrict__ A,
    const float* __restrict__ B0, const float* __restrict__ B1,
    const float* __restrict__ bias0, const float* __restrict__ bias1,
    float* __restrict__ C0, float* __restrict__ C1,
    int K)
{
    extern __shared__ uint32_t smq[];
    uint32_t* As = smq;
    uint32_t* Bs = smq + 128 * 36;

    int dir = blockIdx.x >> 2;
    int nt  = blockIdx.x & 3;
    int mt  = blockIdx.y;
    const float* Ap = A + (size_t)mt * 128 * K;
    const float* Bp = (dir ? B1 : B0) + (size_t)nt * 256 * K;
    const float* bi = (dir ? bias1 : bias0) + nt * 256;
    float* Cp = (dir ? C1 : C0) + (size_t)mt * 128 * G4 + nt * 256;

    int tid = threadIdx.x;
    int warp = tid >> 5, lane = tid & 31;
    int wm = warp & 1, wn = warp >> 1;
    int lr = lane >> 2, lc = lane & 3;

    float c[4][8][4];
#pragma unroll
    for (int mi = 0; mi < 4; mi++)
#pragma unroll
        for (int ni = 0; ni < 8; ni++)
#pragma unroll
            for (int j = 0; j < 4; j++) c[mi][ni][j] = 0.f;

    int nkt = K >> 5;
    for (int kt = 0; kt < nkt; kt++) {
        __syncthreads();
#pragma unroll
        for (int it = 0; it < 4; it++) {
            int i = tid + it * 256;
            int row = i >> 3, c4 = i & 7;
            float4 v = *(const float4*)(Ap + (size_t)row * K + kt * 32 + c4 * 4);
            uint32_t* d = As + row * 36 + c4 * 4;
            d[0] = tf32r(v.x); d[1] = tf32r(v.y); d[2] = tf32r(v.z); d[3] = tf32r(v.w);
        }
#pragma unroll
        for (int it = 0; it < 8; it++) {
            int i = tid + it * 256;
            int row = i >> 3, c4 = i & 7;
            float4 v = *(const float4*)(Bp + (size_t)row * K + kt * 32 + c4 * 4);
            uint32_t* d = Bs + row * 36 + c4 * 4;
            d[0] = tf32r(v.x); d[1] = tf32r(v.y); d[2] = tf32r(v.z); d[3] = tf32r(v.w);
        }
        __syncthreads();

#pragma unroll
        for (int kk = 0; kk < 4; kk++) {
            int k0 = kk * 8;
            uint32_t a[4][4];
#pragma unroll
            for (int mi = 0; mi < 4; mi++) {
                int r = wm * 64 + mi * 16 + lr;
                a[mi][0] = As[r * 36 + k0 + lc];
                a[mi][1] = As[(r + 8) * 36 + k0 + lc];
                a[mi][2] = As[r * 36 + k0 + lc + 4];
                a[mi][3] = As[(r + 8) * 36 + k0 + lc + 4];
            }
            uint32_t b[8][2];
#pragma unroll
            for (int ni = 0; ni < 8; ni++) {
                int n = wn * 64 + ni * 8 + lr;
                b[ni][0] = Bs[n * 36 + k0 + lc];
                b[ni][1] = Bs[n * 36 + k0 + lc + 4];
            }
#pragma unroll
            for (int mi = 0; mi < 4; mi++)
#pragma unroll
                for (int ni = 0; ni < 8; ni++)
                    MMA_TF32(c[mi][ni], a[mi], b[ni]);
        }
    }

#pragma unroll
    for (int mi = 0; mi < 4; mi++) {
        int r0 = wm * 64 + mi * 16 + lr;
#pragma unroll
        for (int ni = 0; ni < 8; ni++) {
            int col = wn * 64 + ni * 8 + 2 * lc;
            float bx = bi[col], by = bi[col + 1];
            *(float2*)(Cp + (size_t)r0 * G4 + col) =
                make_float2(c[mi][ni][0] + bx, c[mi][ni][1] + by);
            *(float2*)(Cp + (size_t)(r0 + 8) * G4 + col) =
                make_float2(c[mi][ni][2] + bx, c[mi][ni][3] + by);
        }
    }
}

// ---------------- prep kernels ----------------
__global__ void prep_wihX(const float* __restrict__ wf, const float* __restrict__ wb) {
    int i = blockIdx.x * 256 + threadIdx.x;
    if (i >= G4 * HID) return;
    int row = i / HID, col = i - row * HID;
    int u = row >> 2, g = row & 3;
    int src = (g * LHU + u) * HID + col;
    g_wihX[0][i] = wf[src]; g_wihX[1][i] = wb[src];
}
__global__ void prep_misc(const float* __restrict__ bf, const float* __restrict__ bb,
                          const float* __restrict__ wf, const float* __restrict__ wb) {
    int i = blockIdx.x * 256 + threadIdx.x;
    if (i < G4) {
        int u = i >> 2, g = i & 3;
        g_biasX[0][i] = bf[g * LHU + u]; g_biasX[1][i] = bb[g * LHU + u];
    }
    if (i < G4 * LHU) {
        int row = i >> 8, k = i & 255;
        int u = row >> 2, g = row & 3;
        int src = (g * LHU + u) * LHU + k;
        g_WhhHi[0][i] = __uint_as_float(tf32r(wf[src]));
        g_WhhHi[1][i] = __uint_as_float(tf32r(wb[src]));
    }
}
__global__ void prep_sent(const float* __restrict__ wsf, const float* __restrict__ wsb) {
    int i = blockIdx.x * 256 + threadIdx.x;
    if (i >= LHU * LHU * 4) return;
    int g = i & 3, u = (i >> 2) & 255, k = i >> 10;
    int src = (g * LHU + u) * LHU + k;
    g_WshhX[0][i] = wsf[src]; g_WshhX[1][i] = wsb[src];
}

// ---------------- persistent tensorized word BiLSTM, v4: cluster-8 DSMEM h-exchange ----------------
// 16 clusters of 8 CTAs; cluster = (dir, mt) group, rank = nt (32 u-cols each).
// h never touches global: epilogue pushes tf32(h) directly into all 8 CTAs' A buffers
// (double-buffered) via st.shared::cluster; one barrier.cluster per step.
// Smem: Bs 8x[128][36] + A[2] x 8x[32][36] = 221184 B.
#define WP_SMEM ((8 * 128 * 36 + 2 * 8 * 32 * 36) * 4)
__global__ void __launch_bounds__(256) __cluster_dims__(8, 1, 1)
word_persist(const int* __restrict__ mask) {
    extern __shared__ uint32_t smw[];
    uint32_t* Bs = smw;                       // 8 * 4608
    uint32_t* A0 = smw + 8 * 4608;            // 8 * 1152
    // A1 = A0 + 9216

    int cta = blockIdx.x;
    int nt  = cta & 7;            // cluster rank
    int gid = cta >> 3;
    int dir = gid >> 3;
    int mt  = gid & 7;
    int tid = threadIdx.x;
    int w   = tid >> 5, lane = tid & 31;
    int wm  = w & 1, wn = w >> 1;
    int lr  = lane >> 2, lc = lane & 3;
    int odd = lc & 1;

    // stage W slice once
    const float* Bsrc = g_WhhHi[dir] + (size_t)(nt * 128) * LHU;
#pragma unroll 4
    for (int i = tid; i < 128 * 64; i += 256) {
        int r = i >> 6, c4 = i & 63;
        float4 v = *(const float4*)(Bsrc + r * 256 + c4 * 4);
        int k = c4 * 4, ch = k >> 5, kin = k & 31;
        *(float4*)(Bs + ch * 4608 + r * 36 + kin) = v;
    }
    // zero A buffer 0 (h0 = 0)
    for (int i = tid; i < 8 * 1152; i += 256) A0[i] = 0;

    // DSMEM rank bases (mapa is offset-preserving)
    uint32_t sbase = (uint32_t)__cvta_generic_to_shared(smw);
    uint32_t rankBase[8];
#pragma unroll
    for (int r = 0; r < 8; r++)
        asm("mapa.shared::cluster.u32 %0, %1, %2;" : "=r"(rankBase[r]) : "r"(sbase), "r"(r));
    // this thread's element offset within an A buffer (bytes): chunk nt, row rloc, col base
    int rloc = wm * 16 + lr + (odd ? 8 : 0);
    uint32_t aoff0 = (uint32_t)((8 * 4608 + nt * 1152 + rloc * 36 + wn * 8 + (lc >> 1)) * 4);

    // per-thread epilogue constants/state: ONE seq, 4 u-cols
    int seqE = mt * 32 + rloc;
    int uE   = nt * 32 + wn * 8 + (lc >> 1);
    uint32_t mb[4];
    {
        uint32_t b0 = 0, b1 = 0, b2 = 0, b3 = 0;
        for (int j = 0; j < 32; j++) {
            b0 |= (uint32_t)(mask[seqE * TLEN + j]      != 0) << j;
            b1 |= (uint32_t)(mask[seqE * TLEN + 32 + j] != 0) << j;
            b2 |= (uint32_t)(mask[seqE * TLEN + 64 + j] != 0) << j;
            b3 |= (uint32_t)(mask[seqE * TLEN + 96 + j] != 0) << j;
        }
        mb[0] = b0; mb[1] = b1; mb[2] = b2; mb[3] = b3;
    }
    float cntE = (float)(__popc(mb[0]) + __popc(mb[1]) + __popc(mb[2]) + __popc(mb[3]));
    float c8[4], pool8[4];
#pragma unroll
    for (int ni = 0; ni < 4; ni++) { c8[ni] = 0.f; pool8[ni] = 0.f; }

    const float* Gd = g_G[dir];
    float4 Gpre[4];
    {
        int t0 = dir ? (TLEN - 1) : 0;
#pragma unroll
        for (int ni = 0; ni < 4; ni++)
            Gpre[ni] = *(const float4*)(Gd + ((size_t)seqE * TLEN + t0) * G4 + 4 * (uE + 2 * ni));
    }
    __syncthreads();
    CLUSTER_SYNC();   // all CTAs initialized before any peer pushes h

    int buf = 0;
    for (int step = 0; step < TLEN; step++) {
        int t = dir ? (TLEN - 1 - step) : step;
        const uint32_t* Ab = A0 + buf * 9216;

        float acc[4][4];
#pragma unroll
        for (int ni = 0; ni < 4; ni++)
#pragma unroll
            for (int j = 0; j < 4; j++) acc[ni][j] = 0.f;

#pragma unroll
        for (int ch = 0; ch < 8; ch++) {
            const uint32_t* Ah = Ab + ch * 1152 + wm * 16 * 36;
            const uint32_t* Bc = Bs + ch * 4608 + wn * 32 * 36;
#pragma unroll
            for (int kk = 0; kk < 4; kk++) {
                int k0 = kk * 8;
                uint32_t aH[4];
                aH[0] = Ah[lr * 36 + k0 + lc];
                aH[1] = Ah[(lr + 8) * 36 + k0 + lc];
                aH[2] = Ah[lr * 36 + k0 + lc + 4];
                aH[3] = Ah[(lr + 8) * 36 + k0 + lc + 4];
                uint32_t b[4][2];
#pragma unroll
                for (int ni = 0; ni < 4; ni++) {
                    int n = ni * 8 + lr;
                    b[ni][0] = Bc[n * 36 + k0 + lc];
                    b[ni][1] = Bc[n * 36 + k0 + lc + 4];
                }
#pragma unroll
                for (int ni = 0; ni < 4; ni++)
                    MMA_TF32(acc[ni], aH, b[ni]);
            }
        }

        // epilogue: gates, state, pool; push tf32(h) to all 8 cluster CTAs
        {
            float mk = (float)((mb[t >> 5] >> (t & 31)) & 1u);
            uint32_t hr[4];
#pragma unroll
            for (int ni = 0; ni < 4; ni++) {
                float x0 = acc[ni][0], x1 = acc[ni][1];
                float x2 = acc[ni][2], x3 = acc[ni][3];
                float r0 = __shfl_xor_sync(0xffffffff, x0, 1);
                float r1 = __shfl_xor_sync(0xffffffff, x1, 1);
                float r2 = __shfl_xor_sync(0xffffffff, x2, 1);
                float r3 = __shfl_xor_sync(0xffffffff, x3, 1);
                float gi, gf, gg, go;
                if (!odd) { gi = x0; gf = x1; gg = r0; go = r1; }
                else      { gi = r2; gf = r3; gg = x2; go = x3; }
                float4 Gv = Gpre[ni];
                float iv = sigf(gi + Gv.x);
                float fv = sigf(gf + Gv.y);
                float gv = tanh_(gg + Gv.z);
                float ov = sigf(go + Gv.w);
                float cc2 = fv * c8[ni] + iv * gv;
                c8[ni] = cc2;
                float hn = ov * tanh_(cc2);
                pool8[ni] += mk * hn;
                hr[ni] = tf32r(hn);
            }
            if (step + 1 < TLEN) {
                uint32_t boff = aoff0 + (uint32_t)((buf ^ 1) * 9216 * 4);
#pragma unroll
                for (int r = 0; r < 8; r++) {
                    uint32_t ad = rankBase[r] + boff;
                    asm volatile("st.shared::cluster.u32 [%0], %1;" :: "r"(ad),      "r"(hr[0]) : "memory");
                    asm volatile("st.shared::cluster.u32 [%0], %1;" :: "r"(ad + 8),  "r"(hr[1]) : "memory");
                    asm volatile("st.shared::cluster.u32 [%0], %1;" :: "r"(ad + 16), "r"(hr[2]) : "memory");
                    asm volatile("st.shared::cluster.u32 [%0], %1;" :: "r"(ad + 24), "r"(hr[3]) : "memory");
                }
                // prefetch next-step G (hides behind cluster barrier)
                int t2 = dir ? (TLEN - 2 - step) : (step + 1);
#pragma unroll
                for (int ni = 0; ni < 4; ni++)
                    Gpre[ni] = *(const float4*)(Gd + ((size_t)seqE * TLEN + t2) * G4 + 4 * (uE + 2 * ni));
            }
        }

        if (step != TLEN - 1) CLUSTER_SYNC();
        buf ^= 1;
    }

    // masked mean -> emb
#pragma unroll
    for (int ni = 0; ni < 4; ni++)
        g_emb[seqE * (2 * LHU) + dir * LHU + uE + 2 * ni] =
            (cntE > 0.f) ? (pool8[ni] / cntE) : 0.f;
}

// ---------------- sentence-level LSTM (fwd scan + bwd single step) ----------------
__device__ __forceinline__ u64 pack2(float lo, float hi) {
    u64 r;
    asm("mov.b64 %0, {%1, %2};" : "=l"(r) : "r"(__float_as_uint(lo)), "r"(__float_as_uint(hi)));
    return r;
}
__device__ __forceinline__ u64 dup2(float x) { return pack2(x, x); }
__device__ __forceinline__ void fma2(u64& a, u64 b, u64 c) {
    asm("fma.rn.f32x2 %0, %1, %2, %0;" : "+l"(a) : "l"(b), "l"(c));
}
__device__ __forceinline__ float2 unpack2(u64 v) {
    unsigned lo, hi;
    asm("mov.b64 {%0, %1}, %2;" : "=r"(lo), "=r"(hi) : "l"(v));
    return make_float2(__uint_as_float(lo), __uint_as_float(hi));
}
__global__ void __launch_bounds__(256) sent_lstm() {
    int b = blockIdx.x, u = threadIdx.x;
    __shared__ float h[LHU];
    h[u] = 0.f;
    float c = 0.f;
    __syncthreads();

    const ulonglong2* W2 = (const ulonglong2*)g_WshhX[0];
    for (int t = 0; t < NSENT; t++) {
        const float* gp = g_Gs[0] + (size_t)(b * NSENT + t) * G4;
        u64 aif = pack2(gp[u],           gp[LHU + u]);
        u64 ago = pack2(gp[2 * LHU + u], gp[3 * LHU + u]);
#pragma unroll 8
        for (int k = 0; k < LHU; k++) {
            ulonglong2 w = W2[k * LHU + u];
            u64 hd = dup2(h[k]);
            fma2(aif, w.x, hd);
            fma2(ago, w.y, hd);
        }
        float2 v1 = unpack2(aif), v2 = unpack2(ago);
        float cc = sigf(v1.y) * c + sigf(v1.x) * tanh_(v2.x);
        c = cc;
        float hn = sigf(v2.y) * tanh_(cc);
        __syncthreads();
        h[u] = hn;
        __syncthreads();
    }
    g_final[b * 2 * LHU + u] = h[u];

    const float* gp = g_Gs[1] + (size_t)(b * NSENT + NSENT - 1) * G4;
    float cc = sigf(gp[u]) * tanh_(gp[2 * LHU + u]);
    g_final[b * 2 * LHU + LHU + u] = sigf(gp[3 * LHU + u]) * tanh_(cc);
}

// ---------------- classifier ----------------
__global__ void classify(const float* __restrict__ cw, const float* __restrict__ cb,
                         float* __restrict__ out) {
    int tid = threadIdx.x;
    if (tid >= 32) return;
    int b = tid >> 2, cc = tid & 3;
    float s = cb[cc];
    for (int k = 0; k < 2 * LHU; k++)
        s += g_final[b * 2 * LHU + k] * cw[cc * 2 * LHU + k];
    out[b * 4 + cc] = s;
}

// ---------------- launch ----------------
extern "C" void kernel_launch(void* const* d_in, const int* in_sizes, int n_in,
                              void* d_out, int out_size) {
    const float* hidden  = (const float*)d_in[0];
    const int*   amask   = (const int*)  d_in[1];
    const float* wl_ih_f = (const float*)d_in[2];
    const float* wl_hh_f = (const float*)d_in[3];
    const float* wl_b_f  = (const float*)d_in[4];
    const float* wl_ih_b = (const float*)d_in[5];
    const float* wl_hh_b = (const float*)d_in[6];
    const float* wl_b_b  = (const float*)d_in[7];
    const float* ws_ih_f = (const float*)d_in[8];
    const float* ws_hh_f = (const float*)d_in[9];
    const float* ws_b_f  = (const float*)d_in[10];
    const float* ws_ih_b = (const float*)d_in[11];
    const float* ws_hh_b = (const float*)d_in[12];
    const float* ws_b_b  = (const float*)d_in[13];
    const float* cls_w   = (const float*)d_in[14];
    const float* cls_b   = (const float*)d_in[15];
    float* out = (float*)d_out;

    float *G0, *Gs0, *emb, *wihX0, *biasX0;
    cudaGetSymbolAddress((void**)&G0,     g_G);
    cudaGetSymbolAddress((void**)&Gs0,    g_Gs);
    cudaGetSymbolAddress((void**)&emb,    g_emb);
    cudaGetSymbolAddress((void**)&wihX0,  g_wihX);
    cudaGetSymbolAddress((void**)&biasX0, g_biasX);
    float* G1     = G0    + (size_t)S_TOT * TLEN * G4;
    float* Gs1    = Gs0   + (size_t)S_TOT * G4;
    float* wihX1  = wihX0 + (size_t)G4 * HID;
    float* biasX1 = biasX0 + G4;

    cudaFuncSetAttribute(mma_gemm,     cudaFuncAttributeMaxDynamicSharedMemorySize, GEMM_SMEM);
    cudaFuncSetAttribute(word_persist, cudaFuncAttributeMaxDynamicSharedMemorySize, WP_SMEM);

    // #1, #2: prep
    prep_wihX<<<(G4 * HID + 255) / 256, 256>>>(wl_ih_f, wl_ih_b);
    prep_misc<<<(G4 * LHU + 255) / 256, 256>>>(wl_b_f, wl_b_b, wl_hh_f, wl_hh_b);
    // #3: word pre-gates (interleaved cols)
    mma_gemm<<<dim3(8, (S_TOT * TLEN) / 128), 256, GEMM_SMEM>>>(
        hidden, wihX0, wihX1, biasX0, biasX1, G0, G1, HID);
    // #4: persistent tensorized word BiLSTM, cluster-8 DSMEM exchange (profiled)
    word_persist<<<NCTA, 256, WP_SMEM>>>(amask);
    // #5-#8
    prep_sent<<<(LHU * LHU * 4 + 255) / 256, 256>>>(ws_hh_f, ws_hh_b);
    mma_gemm<<<dim3(8, S_TOT / 128), 256, GEMM_SMEM>>>(
        emb, ws_ih_f, ws_ih_b, ws_b_f, ws_b_b, Gs0, Gs1, 2 * LHU);
    sent_lstm<<<BATCH, 256>>>();
    classify<<<1, 32>>>(cls_w, cls_b, out);
}